// round 1
// baseline (speedup 1.0000x reference)
#include <cuda_runtime.h>

// Problem constants (fixed by the reference: BATCH=8, SEQ=512, D_MODEL=512, MAX_LEN=512)
#define BATCH 8
#define SEQ   512
#define DM    512

// Scratch for the coefficient matrix C: C[b,i,m]
//   m==0    : sum_{j>=i} q[b,i,j]   (all shifts clipped to 0)
//   1<=m<=i : q[b,i,i-m]
//   m> i    : 0
__device__ float g_C[BATCH * SEQ * DM];

// ---------------------------------------------------------------------------
// Kernel 1: build C. One block per (b,i) row.
// ---------------------------------------------------------------------------
__global__ __launch_bounds__(128) void build_c_kernel(const float* __restrict__ q) {
    const int row = blockIdx.x;          // b*SEQ + i
    const int i   = row & (SEQ - 1);
    const float* __restrict__ qrow = q   + (size_t)row * DM;
    float*       __restrict__ crow = g_C + (size_t)row * DM;

    __shared__ float sq[DM];
    __shared__ float red[128];

    const int t = threadIdx.x;
    float partial = 0.0f;
    #pragma unroll
    for (int j = t; j < DM; j += 128) {
        float v = qrow[j];
        sq[j] = v;
        if (j >= i) partial += v;
    }
    red[t] = partial;
    __syncthreads();
    #pragma unroll
    for (int s = 64; s > 0; s >>= 1) {
        if (t < s) red[t] += red[t + s];
        __syncthreads();
    }
    const float suffix = red[0];

    #pragma unroll
    for (int m = t; m < DM; m += 128) {
        float v;
        if (m == 0)      v = suffix;
        else if (m <= i) v = sq[i - m];
        else             v = 0.0f;
        crow[m] = v;
    }
}

// ---------------------------------------------------------------------------
// Kernel 2: fused GEMM
//   out[b,i,n] = sum_d q[b,i,d] * k[b,n,d]   (phase 0: NT, per-batch K)
//             + sum_m C[b,i,m] * E[m,n]      (phase 1: NN, shared E)
// 64x64 tile, BK=16, 256 threads, 4x4 microtile per thread.
// ---------------------------------------------------------------------------
#define BM 64
#define BN 64
#define BK 16
#define TM 4
#define TN 4

__global__ __launch_bounds__(256) void fused_gemm_kernel(
    const float* __restrict__ q,
    const float* __restrict__ k,
    const float* __restrict__ E,
    float* __restrict__ out)
{
    const int b  = blockIdx.z;
    const int m0 = blockIdx.y * BM;
    const int n0 = blockIdx.x * BN;

    const float* __restrict__ Qb = q   + (size_t)b * SEQ * DM;
    const float* __restrict__ Kb = k   + (size_t)b * SEQ * DM;
    const float* __restrict__ Cb = g_C + (size_t)b * SEQ * DM;

    __shared__ float As[BK][BM + 4];   // +4 keeps float4 alignment of rows
    __shared__ float Bs[BK][BN + 4];

    const int tid = threadIdx.x;
    const int tx  = tid & 15;          // N direction (16)
    const int ty  = tid >> 4;          // M direction (16)

    float acc[TM][TN] = {};

    #pragma unroll
    for (int phase = 0; phase < 2; phase++) {
        const float* __restrict__ A = (phase == 0) ? Qb : Cb;

        for (int k0 = 0; k0 < DM; k0 += BK) {
            // ---- load A tile (BM x BK), store transposed As[k][m] ----
            {
                const int ak  = tid & 15;
                const int amb = tid >> 4;
                #pragma unroll
                for (int r = 0; r < 4; r++) {
                    const int am = amb + r * 16;
                    As[ak][am] = A[(size_t)(m0 + am) * DM + (k0 + ak)];
                }
            }
            // ---- load B tile, store Bs[k][n] ----
            if (phase == 0) {
                // K-major operand: Bs[kk][n] = Kb[(n0+n)*DM + k0+kk]
                const int bk = tid & 15;
                const int nb = tid >> 4;
                #pragma unroll
                for (int r = 0; r < 4; r++) {
                    const int n = nb + r * 16;
                    Bs[bk][n] = Kb[(size_t)(n0 + n) * DM + (k0 + bk)];
                }
            } else {
                // E is [K, N] row-major: coalesced along n
                const int nn = tid & 63;
                const int kb = tid >> 6;      // 0..3
                #pragma unroll
                for (int r = 0; r < 4; r++) {
                    const int kk = kb + r * 4;
                    Bs[kk][nn] = E[(size_t)(k0 + kk) * DM + (n0 + nn)];
                }
            }
            __syncthreads();

            // ---- compute ----
            #pragma unroll
            for (int kk = 0; kk < BK; kk++) {
                const float4 ra = *reinterpret_cast<const float4*>(&As[kk][ty * TM]);
                const float4 rb = *reinterpret_cast<const float4*>(&Bs[kk][tx * TN]);
                const float a_[TM] = {ra.x, ra.y, ra.z, ra.w};
                const float b_[TN] = {rb.x, rb.y, rb.z, rb.w};
                #pragma unroll
                for (int ii = 0; ii < TM; ii++)
                    #pragma unroll
                    for (int jj = 0; jj < TN; jj++)
                        acc[ii][jj] += a_[ii] * b_[jj];
            }
            __syncthreads();
        }
    }

    // ---- write out ----
    float* __restrict__ Ob = out + (size_t)b * SEQ * SEQ;
    #pragma unroll
    for (int ii = 0; ii < TM; ii++) {
        const int m = m0 + ty * TM + ii;
        float4 v = make_float4(acc[ii][0], acc[ii][1], acc[ii][2], acc[ii][3]);
        *reinterpret_cast<float4*>(&Ob[(size_t)m * SEQ + n0 + tx * TN]) = v;
    }
}

// ---------------------------------------------------------------------------
extern "C" void kernel_launch(void* const* d_in, const int* in_sizes, int n_in,
                              void* d_out, int out_size) {
    const float* q = (const float*)d_in[0];
    const float* k = (const float*)d_in[1];
    const float* E = (const float*)d_in[2];
    float* out = (float*)d_out;

    build_c_kernel<<<BATCH * SEQ, 128>>>(q);

    dim3 grid(SEQ / BN, SEQ / BM, BATCH);
    fused_gemm_kernel<<<grid, 256>>>(q, k, E, out);
}

// round 5
// speedup vs baseline: 3.1749x; 3.1749x over previous
#include <cuda_runtime.h>
#include <cstdint>

#define BATCH 8
#define SEQ   512
#define DM    512

// ---------------------------------------------------------------------------
// Scratch (tf32-rounded operands), 128B aligned for cp.async
// ---------------------------------------------------------------------------
__device__ __align__(128) float g_Qr[BATCH * SEQ * DM];   // rounded Q
__device__ __align__(128) float g_Kr[BATCH * SEQ * DM];   // rounded K
__device__ __align__(128) float g_C [BATCH * SEQ * DM];   // rounded coeff matrix
__device__ __align__(128) float g_Et[SEQ * DM];           // rounded E^T [n][m]

// cvt.rna.tf32.f32 destination is a .b32 register (PTX ISA), so use "=r".
__device__ __forceinline__ float rna_tf32(float x) {
    uint32_t r;
    asm("cvt.rna.tf32.f32 %0, %1;" : "=r"(r) : "f"(x));
    return __uint_as_float(r);
}

__device__ __forceinline__ void cpa16(uint32_t dst, const void* src) {
    asm volatile("cp.async.cg.shared.global [%0], [%1], 16;" :: "r"(dst), "l"(src));
}
__device__ __forceinline__ void cpa_commit() {
    asm volatile("cp.async.commit_group;" ::: "memory");
}
template <int N> __device__ __forceinline__ void cpa_wait() {
    asm volatile("cp.async.wait_group %0;" :: "n"(N) : "memory");
}
__device__ __forceinline__ uint32_t smem_u32(const void* p) {
    uint32_t a;
    asm("{ .reg .u64 t; cvta.to.shared.u64 t, %1; cvt.u32.u64 %0, t; }" : "=r"(a) : "l"(p));
    return a;
}

// m16n8k8 tf32 MMA (sm_80+, compiles for plain compute_100 target)
__device__ __forceinline__ void mma_m16n8k8(float* d, const uint32_t* a, const uint32_t* b) {
    asm volatile(
        "mma.sync.aligned.m16n8k8.row.col.f32.tf32.tf32.f32 "
        "{%0,%1,%2,%3}, {%4,%5,%6,%7}, {%8,%9}, {%0,%1,%2,%3};"
        : "+f"(d[0]), "+f"(d[1]), "+f"(d[2]), "+f"(d[3])
        : "r"(a[0]), "r"(a[1]), "r"(a[2]), "r"(a[3]), "r"(b[0]), "r"(b[1]));
}

// ---------------------------------------------------------------------------
// Prep 1: rounded Q copy + coefficient matrix C. One block per (b,i).
//   C[b,i,0]    = sum_{j>=i} q[b,i,j]
//   C[b,i,m<=i] = q[b,i,i-m] ;  C[b,i,m>i] = 0
// ---------------------------------------------------------------------------
__global__ __launch_bounds__(128) void build_qc_kernel(const float* __restrict__ q) {
    const int row = blockIdx.x;
    const int i   = row & (SEQ - 1);
    const float* __restrict__ qrow = q    + (size_t)row * DM;
    float* __restrict__ qr         = g_Qr + (size_t)row * DM;
    float* __restrict__ cr         = g_C  + (size_t)row * DM;

    __shared__ float sq[DM];
    __shared__ float red[128];
    const int t = threadIdx.x;

    float partial = 0.0f;
    #pragma unroll
    for (int j = t; j < DM; j += 128) {
        float v = qrow[j];
        sq[j] = v;
        qr[j] = rna_tf32(v);
        if (j >= i) partial += v;
    }
    red[t] = partial;
    __syncthreads();
    #pragma unroll
    for (int s = 64; s > 0; s >>= 1) {
        if (t < s) red[t] += red[t + s];
        __syncthreads();
    }
    const float suffix = red[0];

    #pragma unroll
    for (int m = t; m < DM; m += 128) {
        float v = (m == 0) ? suffix : ((m <= i) ? sq[i - m] : 0.0f);
        cr[m] = rna_tf32(v);
    }
}

// Prep 2: rounded K copy
__global__ void prep_k_kernel(const float4* __restrict__ k) {
    float4* __restrict__ kr = reinterpret_cast<float4*>(g_Kr);
    const int n = BATCH * SEQ * DM / 4;
    for (int idx = blockIdx.x * blockDim.x + threadIdx.x; idx < n;
         idx += gridDim.x * blockDim.x) {
        float4 v = k[idx];
        v.x = rna_tf32(v.x); v.y = rna_tf32(v.y);
        v.z = rna_tf32(v.z); v.w = rna_tf32(v.w);
        kr[idx] = v;
    }
}

// Prep 3: rounded E transpose. Et[n][m] = rna(E[m][n])
__global__ void prep_et_kernel(const float* __restrict__ E) {
    __shared__ float tile[32][33];
    const int bx = blockIdx.x * 32, by = blockIdx.y * 32;
    const int tx = threadIdx.x, ty = threadIdx.y;
    #pragma unroll
    for (int i = 0; i < 4; i++) {
        int r = ty + i * 8;
        tile[r][tx] = E[(size_t)(by + r) * DM + bx + tx];
    }
    __syncthreads();
    #pragma unroll
    for (int i = 0; i < 4; i++) {
        int r = ty + i * 8;
        g_Et[(size_t)(bx + r) * DM + by + tx] = rna_tf32(tile[tx][r]);
    }
}

// ---------------------------------------------------------------------------
// Main GEMM: out[b][m][n] = sum_{kk<1024} A'[m][kk] * B'[n][kk]
//   A' = [Qr | C] (per batch), B' = [Kr | Et]
// 128x128 CTA tile, BK=32, 3-stage cp.async, 8 warps (2x4), warp tile 64x32.
// ---------------------------------------------------------------------------
#define BM 128
#define BN 128
#define BKF 32
#define PAD 4
#define ROWSZ (BKF + PAD)              // 36 floats per smem row
#define TILEF (BM * ROWSZ)             // 4608 floats per operand tile
#define STAGEF (2 * TILEF)             // A + B
#define NSTAGE 3
#define SMEM_BYTES (NSTAGE * STAGEF * 4)   // 110,592 B

__device__ __forceinline__ void load_stage(int s, int buf, int b, int m0, int n0,
                                           uint32_t smem_base, int tid) {
    const int kg0 = (s & 15) * BKF;
    const float* Asrc;
    const float* Bsrc;
    if (s < 16) {
        Asrc = g_Qr + ((size_t)(b * SEQ + m0)) * DM + kg0;
        Bsrc = g_Kr + ((size_t)(b * SEQ + n0)) * DM + kg0;
    } else {
        Asrc = g_C  + ((size_t)(b * SEQ + m0)) * DM + kg0;
        Bsrc = g_Et + (size_t)n0 * DM + kg0;
    }
    const uint32_t abase = smem_base + buf * (STAGEF * 4);
    const uint32_t bbase = abase + TILEF * 4;

    // each tile: 128 rows x 8 float4 = 1024 chunks; 256 threads x 4
    #pragma unroll
    for (int i = 0; i < 4; i++) {
        const int e = tid + i * 256;
        const int r = e >> 3;
        const int f = e & 7;
        cpa16(abase + (uint32_t)(r * ROWSZ + f * 4) * 4, Asrc + (size_t)r * DM + f * 4);
    }
    #pragma unroll
    for (int i = 0; i < 4; i++) {
        const int e = tid + i * 256;
        const int r = e >> 3;
        const int f = e & 7;
        cpa16(bbase + (uint32_t)(r * ROWSZ + f * 4) * 4, Bsrc + (size_t)r * DM + f * 4);
    }
}

__global__ __launch_bounds__(256, 1) void gemm_kernel(float* __restrict__ out) {
    extern __shared__ __align__(16) float smem[];
    const uint32_t smem_base = smem_u32(smem);
    const int tid  = threadIdx.x;
    const int wid  = tid >> 5;
    const int lane = tid & 31;
    const int b  = blockIdx.z;
    const int m0 = blockIdx.y * BM;
    const int n0 = blockIdx.x * BN;

    const int wm = (wid >> 2) * 64;    // warp m offset (0 or 64)
    const int wn = (wid & 3) * 32;     // warp n offset (0..96)
    const int grp = lane >> 2;         // 0..7
    const int qk  = lane & 3;          // 0..3

    float acc[4][4][4];
    #pragma unroll
    for (int mi = 0; mi < 4; mi++)
        #pragma unroll
        for (int ni = 0; ni < 4; ni++)
            #pragma unroll
            for (int r = 0; r < 4; r++) acc[mi][ni][r] = 0.0f;

    // prologue
    load_stage(0, 0, b, m0, n0, smem_base, tid); cpa_commit();
    load_stage(1, 1, b, m0, n0, smem_base, tid); cpa_commit();

    #pragma unroll 1
    for (int s = 0; s < 32; s++) {
        if (s >= 30) cpa_wait<0>(); else cpa_wait<1>();
        __syncthreads();
        if (s + 2 < 32) {
            load_stage(s + 2, (s + 2) % 3, b, m0, n0, smem_base, tid);
            cpa_commit();
        }

        const int buf = s - (s / 3) * 3;
        const float* As = smem + buf * STAGEF;
        const float* Bs = As + TILEF;

        #pragma unroll
        for (int k8 = 0; k8 < 4; k8++) {
            const int kk = k8 * 8 + qk;
            uint32_t a[4][4];
            #pragma unroll
            for (int mi = 0; mi < 4; mi++) {
                const int mrow = wm + mi * 16 + grp;
                a[mi][0] = __float_as_uint(As[mrow * ROWSZ + kk]);
                a[mi][1] = __float_as_uint(As[(mrow + 8) * ROWSZ + kk]);
                a[mi][2] = __float_as_uint(As[mrow * ROWSZ + kk + 4]);
                a[mi][3] = __float_as_uint(As[(mrow + 8) * ROWSZ + kk + 4]);
            }
            uint32_t bf[4][2];
            #pragma unroll
            for (int ni = 0; ni < 4; ni++) {
                const int ncol = wn + ni * 8 + grp;
                bf[ni][0] = __float_as_uint(Bs[ncol * ROWSZ + kk]);
                bf[ni][1] = __float_as_uint(Bs[ncol * ROWSZ + kk + 4]);
            }
            #pragma unroll
            for (int mi = 0; mi < 4; mi++)
                #pragma unroll
                for (int ni = 0; ni < 4; ni++)
                    mma_m16n8k8(acc[mi][ni], a[mi], bf[ni]);
        }
    }

    // epilogue: direct float2 stores
    float* __restrict__ Ob = out + (size_t)b * SEQ * SEQ;
    #pragma unroll
    for (int mi = 0; mi < 4; mi++) {
        const int mr = m0 + wm + mi * 16 + grp;
        #pragma unroll
        for (int ni = 0; ni < 4; ni++) {
            const int nc = n0 + wn + ni * 8 + qk * 2;
            float2 v0 = make_float2(acc[mi][ni][0], acc[mi][ni][1]);
            float2 v1 = make_float2(acc[mi][ni][2], acc[mi][ni][3]);
            *reinterpret_cast<float2*>(&Ob[(size_t)mr * SEQ + nc]) = v0;
            *reinterpret_cast<float2*>(&Ob[(size_t)(mr + 8) * SEQ + nc]) = v1;
        }
    }
}

// ---------------------------------------------------------------------------
extern "C" void kernel_launch(void* const* d_in, const int* in_sizes, int n_in,
                              void* d_out, int out_size) {
    const float* q = (const float*)d_in[0];
    const float* k = (const float*)d_in[1];
    const float* E = (const float*)d_in[2];
    float* out = (float*)d_out;

    cudaFuncSetAttribute(gemm_kernel, cudaFuncAttributeMaxDynamicSharedMemorySize, SMEM_BYTES);

    build_qc_kernel<<<BATCH * SEQ, 128>>>(q);
    prep_k_kernel<<<1024, 256>>>((const float4*)k);
    prep_et_kernel<<<dim3(16, 16), dim3(32, 8)>>>(E);

    dim3 grid(SEQ / BN, SEQ / BM, BATCH);
    gemm_kernel<<<grid, 256, SMEM_BYTES>>>(out);
}

// round 7
// speedup vs baseline: 3.5323x; 1.1126x over previous
#include <cuda_runtime.h>
#include <cstdint>

#define BATCH 8
#define SEQ   512
#define DM    512

// ---------------------------------------------------------------------------
// Scratch, stored with within-8-group k-permutation so mma fragment pairs
// (k, k+4) are adjacent: perm(k) = (k & ~7) | ((k&3)<<1) | ((k>>2)&1)
// ---------------------------------------------------------------------------
__device__ __align__(128) float g_Qr[BATCH * SEQ * DM];
__device__ __align__(128) float g_Kr[BATCH * SEQ * DM];
__device__ __align__(128) float g_C [BATCH * SEQ * DM];
__device__ __align__(128) float g_Et[SEQ * DM];

__device__ __forceinline__ int perm8(int k) {
    return (k & ~7) | ((k & 3) << 1) | ((k >> 2) & 1);
}

// cvt.rna.tf32.f32 destination is .b32 (PTX ISA)
__device__ __forceinline__ float rna_tf32(float x) {
    uint32_t r;
    asm("cvt.rna.tf32.f32 %0, %1;" : "=r"(r) : "f"(x));
    return __uint_as_float(r);
}

__device__ __forceinline__ void cpa16(uint32_t dst, const void* src) {
    asm volatile("cp.async.cg.shared.global [%0], [%1], 16;" :: "r"(dst), "l"(src));
}
__device__ __forceinline__ void cpa_commit() {
    asm volatile("cp.async.commit_group;" ::: "memory");
}
template <int N> __device__ __forceinline__ void cpa_wait() {
    asm volatile("cp.async.wait_group %0;" :: "n"(N) : "memory");
}
__device__ __forceinline__ uint32_t smem_u32(const void* p) {
    uint32_t a;
    asm("{ .reg .u64 t; cvta.to.shared.u64 t, %1; cvt.u32.u64 %0, t; }" : "=r"(a) : "l"(p));
    return a;
}

__device__ __forceinline__ void mma_m16n8k8(float* d, const uint32_t* a, const uint32_t* b) {
    asm volatile(
        "mma.sync.aligned.m16n8k8.row.col.f32.tf32.tf32.f32 "
        "{%0,%1,%2,%3}, {%4,%5,%6,%7}, {%8,%9}, {%0,%1,%2,%3};"
        : "+f"(d[0]), "+f"(d[1]), "+f"(d[2]), "+f"(d[3])
        : "r"(a[0]), "r"(a[1]), "r"(a[2]), "r"(a[3]), "r"(b[0]), "r"(b[1]));
}

// ---------------------------------------------------------------------------
// Single merged prep kernel. One block per (b,i) row (4096 blocks, 128 thr):
//   - g_Qr[row][perm(j)] = rna(q[row][j])
//   - g_Kr[row][perm(j)] = rna(k[row][j])
//   - g_C [row][perm(m)] = rna(C-row)   (C[0]=suffix sum, C[m<=i]=q[i-m])
//   - blocks row<512 additionally: g_Et[row][perm(m)] = rna(E[m][row])
// ---------------------------------------------------------------------------
__global__ __launch_bounds__(128) void prep_kernel(const float* __restrict__ q,
                                                   const float* __restrict__ k,
                                                   const float* __restrict__ E) {
    const int row = blockIdx.x;
    const int i   = row & (SEQ - 1);
    const float* __restrict__ qrow = q    + (size_t)row * DM;
    const float* __restrict__ krow = k    + (size_t)row * DM;
    float* __restrict__ qr         = g_Qr + (size_t)row * DM;
    float* __restrict__ kr         = g_Kr + (size_t)row * DM;
    float* __restrict__ cr         = g_C  + (size_t)row * DM;

    __shared__ float sq[DM];
    __shared__ float red[128];
    const int t = threadIdx.x;

    float partial = 0.0f;
    #pragma unroll
    for (int j = t; j < DM; j += 128) {
        float v = qrow[j];
        sq[j] = v;
        qr[perm8(j)] = rna_tf32(v);
        kr[perm8(j)] = rna_tf32(krow[j]);
        if (j >= i) partial += v;
    }
    red[t] = partial;
    __syncthreads();
    #pragma unroll
    for (int s = 64; s > 0; s >>= 1) {
        if (t < s) red[t] += red[t + s];
        __syncthreads();
    }
    const float suffix = red[0];

    #pragma unroll
    for (int m = t; m < DM; m += 128) {
        float v = (m == 0) ? suffix : ((m <= i) ? sq[i - m] : 0.0f);
        cr[perm8(m)] = rna_tf32(v);
    }

    if (row < SEQ) {   // transpose E: Et[n=row][perm(m)] = rna(E[m][n])
        float* __restrict__ et = g_Et + (size_t)row * DM;
        #pragma unroll
        for (int m = t; m < DM; m += 128)
            et[perm8(m)] = rna_tf32(E[(size_t)m * DM + row]);
    }
}

// ---------------------------------------------------------------------------
// Main GEMM: out[b][m][n] = sum_{kk<1024} A'[m][kk] * B'[n][kk]
// 128x128 CTA tile, BK=32, 3-stage cp.async, 8 warps (2x4), warp tile 64x32,
// permuted smem rows + LDS.64 fragment loads, double-buffered fragments.
// ---------------------------------------------------------------------------
#define BM 128
#define BN 128
#define BKF 32
#define ROWSZ 40                        // 32 data floats + 8 pad (conflict-free LDS.64)
#define TILEF (BM * ROWSZ)              // 5120 floats
#define STAGEF (2 * TILEF)
#define NSTAGE 3
#define SMEM_BYTES (NSTAGE * STAGEF * 4)   // 122,880 B

__device__ __forceinline__ void load_stage(int s, int buf, int b, int m0, int n0,
                                           uint32_t smem_base, int tid) {
    const int kg0 = (s & 15) * BKF;
    const float* Asrc;
    const float* Bsrc;
    if (s < 16) {
        Asrc = g_Qr + ((size_t)(b * SEQ + m0)) * DM + kg0;
        Bsrc = g_Kr + ((size_t)(b * SEQ + n0)) * DM + kg0;
    } else {
        Asrc = g_C  + ((size_t)(b * SEQ + m0)) * DM + kg0;
        Bsrc = g_Et + (size_t)n0 * DM + kg0;
    }
    const uint32_t abase = smem_base + buf * (STAGEF * 4);
    const uint32_t bbase = abase + TILEF * 4;

    // each tile: 128 rows x 8 float4 chunks; 256 threads x 4 chunks
    #pragma unroll
    for (int i = 0; i < 4; i++) {
        const int e = tid + i * 256;
        const int r = e >> 3;
        const int f = e & 7;
        cpa16(abase + (uint32_t)(r * ROWSZ + f * 4) * 4, Asrc + (size_t)r * DM + f * 4);
    }
    #pragma unroll
    for (int i = 0; i < 4; i++) {
        const int e = tid + i * 256;
        const int r = e >> 3;
        const int f = e & 7;
        cpa16(bbase + (uint32_t)(r * ROWSZ + f * 4) * 4, Bsrc + (size_t)r * DM + f * 4);
    }
}

struct Frag {
    uint32_t a[4][4];
    uint32_t b[4][2];
};

__device__ __forceinline__ void load_frag(Frag& fr, const float* As, const float* Bs,
                                          int k8, int wm, int wn, int grp, int qk) {
    const int kp = k8 * 8 + qk * 2;     // permuted position of (kk, kk+4)
    #pragma unroll
    for (int mi = 0; mi < 4; mi++) {
        const int mrow = wm + mi * 16 + grp;
        const float2 lo = *reinterpret_cast<const float2*>(&As[mrow * ROWSZ + kp]);
        const float2 hi = *reinterpret_cast<const float2*>(&As[(mrow + 8) * ROWSZ + kp]);
        fr.a[mi][0] = __float_as_uint(lo.x);
        fr.a[mi][1] = __float_as_uint(hi.x);
        fr.a[mi][2] = __float_as_uint(lo.y);
        fr.a[mi][3] = __float_as_uint(hi.y);
    }
    #pragma unroll
    for (int ni = 0; ni < 4; ni++) {
        const int ncol = wn + ni * 8 + grp;
        const float2 bb = *reinterpret_cast<const float2*>(&Bs[ncol * ROWSZ + kp]);
        fr.b[ni][0] = __float_as_uint(bb.x);
        fr.b[ni][1] = __float_as_uint(bb.y);
    }
}

__global__ __launch_bounds__(256, 1) void gemm_kernel(float* __restrict__ out) {
    extern __shared__ __align__(16) float smem[];
    const uint32_t smem_base = smem_u32(smem);
    const int tid  = threadIdx.x;
    const int wid  = tid >> 5;
    const int lane = tid & 31;
    const int b  = blockIdx.z;
    const int m0 = blockIdx.y * BM;
    const int n0 = blockIdx.x * BN;

    const int wm = (wid >> 2) * 64;
    const int wn = (wid & 3) * 32;
    const int grp = lane >> 2;
    const int qk  = lane & 3;

    float acc[4][4][4];
    #pragma unroll
    for (int mi = 0; mi < 4; mi++)
        #pragma unroll
        for (int ni = 0; ni < 4; ni++)
            #pragma unroll
            for (int r = 0; r < 4; r++) acc[mi][ni][r] = 0.0f;

    load_stage(0, 0, b, m0, n0, smem_base, tid); cpa_commit();
    load_stage(1, 1, b, m0, n0, smem_base, tid); cpa_commit();

    Frag fr[2];

    #pragma unroll 1
    for (int s = 0; s < 32; s++) {
        if (s >= 30) cpa_wait<0>(); else cpa_wait<1>();
        __syncthreads();
        if (s + 2 < 32) {
            load_stage(s + 2, (s + 2) % 3, b, m0, n0, smem_base, tid);
            cpa_commit();
        }

        const int buf = s - (s / 3) * 3;
        const float* As = smem + buf * STAGEF;
        const float* Bs = As + TILEF;

        load_frag(fr[0], As, Bs, 0, wm, wn, grp, qk);
        #pragma unroll
        for (int k8 = 0; k8 < 4; k8++) {
            if (k8 < 3)
                load_frag(fr[(k8 + 1) & 1], As, Bs, k8 + 1, wm, wn, grp, qk);
            const Frag& f = fr[k8 & 1];
            #pragma unroll
            for (int mi = 0; mi < 4; mi++)
                #pragma unroll
                for (int ni = 0; ni < 4; ni++)
                    mma_m16n8k8(acc[mi][ni], f.a[mi], f.b[ni]);
        }
    }

    // epilogue
    float* __restrict__ Ob = out + (size_t)b * SEQ * SEQ;
    #pragma unroll
    for (int mi = 0; mi < 4; mi++) {
        const int mr = m0 + wm + mi * 16 + grp;
        #pragma unroll
        for (int ni = 0; ni < 4; ni++) {
            const int nc = n0 + wn + ni * 8 + qk * 2;
            float2 v0 = make_float2(acc[mi][ni][0], acc[mi][ni][1]);
            float2 v1 = make_float2(acc[mi][ni][2], acc[mi][ni][3]);
            *reinterpret_cast<float2*>(&Ob[(size_t)mr * SEQ + nc]) = v0;
            *reinterpret_cast<float2*>(&Ob[(size_t)(mr + 8) * SEQ + nc]) = v1;
        }
    }
}

// ---------------------------------------------------------------------------
extern "C" void kernel_launch(void* const* d_in, const int* in_sizes, int n_in,
                              void* d_out, int out_size) {
    const float* q = (const float*)d_in[0];
    const float* k = (const float*)d_in[1];
    const float* E = (const float*)d_in[2];
    float* out = (float*)d_out;

    cudaFuncSetAttribute(gemm_kernel, cudaFuncAttributeMaxDynamicSharedMemorySize, SMEM_BYTES);

    prep_kernel<<<BATCH * SEQ, 128>>>(q, k, E);

    dim3 grid(SEQ / BN, SEQ / BM, BATCH);
    gemm_kernel<<<grid, 256, SMEM_BYTES>>>(out);
}